// round 8
// baseline (speedup 1.0000x reference)
#include <cuda_runtime.h>
#include <cuda_bf16.h>
#include <cstdint>

// Problem shape (fixed)
#define BB_ 64
#define SS_ 512
#define HH_ 1024
#define LL_ 9

#define TPB 256
#define WARPS 8
#define ROWS_PER_WARP 4
#define ROWS_PER_BLOCK 32
#define NCHUNK 16                 // 512/32 mask chunks
#define KC4 32                    // float4 per chunk per row (512 B)
#define NKC 8                     // k-chunks: 8 * 512B = 4KB per row
#define STAGES 4
#define W_BYTES (LL_ * HH_ * 4)   // 36864

// Transposed weights [L][H], written once
__device__ float g_Wt[LL_ * HH_];

typedef unsigned long long u64;

__device__ __forceinline__ u64 fma2(u64 a, u64 b, u64 c) {
    u64 d;
    asm("fma.rn.f32x2 %0, %1, %2, %3;" : "=l"(d) : "l"(a), "l"(b), "l"(c));
    return d;
}
__device__ __forceinline__ u64 add2(u64 a, u64 b) {
    u64 d;
    asm("add.rn.f32x2 %0, %1, %2;" : "=l"(d) : "l"(a), "l"(b));
    return d;
}
__device__ __forceinline__ float pair_sum(u64 v) {
    float lo = __uint_as_float((unsigned)(v & 0xffffffffull));
    float hi = __uint_as_float((unsigned)(v >> 32));
    return lo + hi;
}

// ---- mbarrier / bulk-copy primitives (sm_100 real-async path) ----
__device__ __forceinline__ void mbar_init(uint32_t a, uint32_t cnt) {
    asm volatile("mbarrier.init.shared.b64 [%0], %1;" :: "r"(a), "r"(cnt) : "memory");
}
__device__ __forceinline__ void mbar_expect_tx(uint32_t a, uint32_t bytes) {
    asm volatile("mbarrier.arrive.expect_tx.shared.b64 _, [%0], %1;"
                 :: "r"(a), "r"(bytes) : "memory");
}
__device__ __forceinline__ void mbar_arrive(uint32_t a) {
    asm volatile("mbarrier.arrive.shared.b64 _, [%0];" :: "r"(a) : "memory");
}
__device__ __forceinline__ void mbar_wait(uint32_t a, uint32_t ph) {
    uint32_t done;
    asm volatile(
        "{\n\t.reg .pred p;\n\t"
        "mbarrier.try_wait.parity.acquire.cta.shared::cta.b64 p, [%1], %2;\n\t"
        "selp.b32 %0, 1, 0, p;\n\t}"
        : "=r"(done) : "r"(a), "r"(ph) : "memory");
    while (!done) {
        asm volatile(
            "{\n\t.reg .pred p;\n\t"
            "mbarrier.try_wait.parity.acquire.cta.shared::cta.b64 p, [%1], %2, 0x989680;\n\t"
            "selp.b32 %0, 1, 0, p;\n\t}"
            : "=r"(done) : "r"(a), "r"(ph) : "memory");
    }
}
__device__ __forceinline__ void bulk_g2s(uint32_t dst, const void* src,
                                         uint32_t bytes, uint32_t mbar) {
    asm volatile(
        "cp.async.bulk.shared::cta.global.mbarrier::complete_tx::bytes [%0], [%1], %2, [%3];"
        :: "r"(dst), "l"(src), "r"(bytes), "r"(mbar) : "memory");
}

// ---------------------------------------------------------------------------
// One-shot: W [H,L] -> g_Wt [L,H]
// ---------------------------------------------------------------------------
__global__ void transpose_W(const float* __restrict__ W) {
    int j = blockIdx.x;
    int k = threadIdx.x;
    g_Wt[j * HH_ + k] = W[k * LL_ + j];
}

// ---------------------------------------------------------------------------
// Main kernel. Block = 32 rows of one batch. x streamed via cp.async.bulk
// (TMA) through a 4-stage mbarrier pipeline; W via one 36 KB bulk copy.
// Half-warp j-split GEMV with f32x2 FMA.
// ---------------------------------------------------------------------------
extern __shared__ float4 dynsmem[];
// [0, 2304)          : Wt as float4 (36 KB)
// [2304, 2304+4096)  : x stages: [stage][row][32 float4] (64 KB)

__global__ __launch_bounds__(TPB, 2)
void bertner_main_kernel(const float* __restrict__ seq,
                         const int* __restrict__ mask,
                         const float* __restrict__ bias,
                         float* __restrict__ out) {
    float4* sW4  = dynsmem;
    float4* xstg = dynsmem + LL_ * 256;

    __shared__ unsigned mbits[NCHUNK];
    __shared__ int msum[NCHUNK];
    __shared__ int ssrc[ROWS_PER_BLOCK];
    __shared__ int snv;
    __shared__ float sb[LL_];
    __shared__ __align__(8) unsigned long long barmem[2 * STAGES + 1];

    int tid  = threadIdx.x;
    int lane = tid & 31;
    int warp = tid >> 5;

    int b  = blockIdx.x >> 4;
    int d0 = (blockIdx.x & 15) * ROWS_PER_BLOCK;

    if (tid < LL_) sb[tid] = bias[tid];

    // ---- per-block mask scan (512 bits) ----
    #pragma unroll
    for (int r = 0; r < 2; r++) {
        int chunk = warp * 2 + r;
        int s = chunk * 32 + lane;
        int m = (mask[b * SS_ + s] != 0);
        unsigned bal = __ballot_sync(0xffffffffu, m);
        if (lane == 0) mbits[chunk] = bal;
    }
    __syncthreads();
    if (tid < NCHUNK) {
        int v = __popc(mbits[tid]);
        #pragma unroll
        for (int off = 1; off < NCHUNK; off <<= 1) {
            int u = __shfl_up_sync(0x0000ffffu, v, off);
            if (tid >= off) v += u;
        }
        msum[tid] = v;
        if (tid == NCHUNK - 1) snv = v;
    }
    __syncthreads();
    int nv = snv;

    if (d0 >= nv) {
        // whole block invalid: softmax(bias) for its 32 rows
        if (tid < ROWS_PER_BLOCK) {
            float l[LL_];
            float mx = -3.402823466e+38f;
            #pragma unroll
            for (int j = 0; j < LL_; j++) { l[j] = sb[j]; mx = fmaxf(mx, l[j]); }
            float ssum = 0.0f;
            #pragma unroll
            for (int j = 0; j < LL_; j++) { l[j] = __expf(l[j] - mx); ssum += l[j]; }
            float inv = __fdividef(1.0f, ssum);
            float* o = out + (size_t)(b * SS_ + d0 + tid) * LL_;
            #pragma unroll
            for (int j = 0; j < LL_; j++) o[j] = l[j] * inv;
        }
        return;
    }

    // ---- source index for this block's 32 rows ----
    if (tid < ROWS_PER_BLOCK) {
        int d = d0 + tid;
        int src = 0;
        if (d < nv) {
            int c = 0, base = 0;
            #pragma unroll
            for (int cc = 0; cc < NCHUNK - 1; cc++)
                if (msum[cc] <= d) { c = cc + 1; base = msum[cc]; }
            unsigned wv = mbits[c];
            int rr = d - base;
            for (int t = 0; t < rr; t++) wv &= wv - 1;
            src = c * 32 + (__ffs(wv) - 1);
        }
        ssrc[tid] = src;
    }

    // ---- mbarrier init ----
    uint32_t barbase = (uint32_t)__cvta_generic_to_shared(barmem);
    #define FULLB(s)  (barbase + (uint32_t)(s) * 8u)
    #define EMPTYB(s) (barbase + (uint32_t)(STAGES + (s)) * 8u)
    #define WBAR      (barbase + (uint32_t)(2 * STAGES) * 8u)
    if (tid == 0) {
        #pragma unroll
        for (int s = 0; s < STAGES; s++) {
            mbar_init(FULLB(s), 1);
            mbar_init(EMPTYB(s), TPB);
        }
        mbar_init(WBAR, 1);
    }
    __syncthreads();   // ssrc + barriers visible

    int nvb = nv - d0; if (nvb > ROWS_PER_BLOCK) nvb = ROWS_PER_BLOCK;
    uint32_t xtx = (uint32_t)nvb * 512u;

    uint32_t wsm = (uint32_t)__cvta_generic_to_shared(sW4);
    uint32_t xsm = (uint32_t)__cvta_generic_to_shared(xstg);

    // producer state (warp 0; lane r owns row r)
    const float* rowp = nullptr;
    bool rowValid = false;
    if (warp == 0) {
        rowValid = (d0 + lane) < nv;
        rowp = seq + (size_t)(b * SS_ + ssrc[lane]) * HH_;
        if (lane == 0) {
            mbar_expect_tx(WBAR, W_BYTES);
            bulk_g2s(wsm, g_Wt, W_BYTES, WBAR);
        }
        // prologue: fill stages 0..3 with chunks 0..3
        #pragma unroll
        for (int c = 0; c < STAGES; c++) {
            if (lane == 0) mbar_expect_tx(FULLB(c), xtx);
            __syncwarp();
            if (rowValid)
                bulk_g2s(xsm + (uint32_t)(c * 1024 + lane * KC4) * 16u,
                         rowp + c * (KC4 * 4), 512u, FULLB(c));
        }
    }

    // ---- compute mapping ----
    int jg = lane >> 4;                     // 0: j0..3, 1: j4..8
    int kl = lane & 15;
    int jbase = jg * 4;
    int rw0 = warp * ROWS_PER_WARP;
    const ulonglong2* sW2 = (const ulonglong2*)sW4;

    u64 acc[ROWS_PER_WARP][5];
    #pragma unroll
    for (int p = 0; p < ROWS_PER_WARP; p++)
        #pragma unroll
        for (int jj = 0; jj < 5; jj++) acc[p][jj] = 0ull;

    mbar_wait(WBAR, 0);                     // W resident

    #pragma unroll
    for (int c = 0; c < NKC; c++) {
        int st = c & (STAGES - 1);
        mbar_wait(FULLB(st), (c >> 2) & 1);

        const ulonglong2* xc = (const ulonglong2*)(xstg + st * 1024);
        #pragma unroll
        for (int s = 0; s < 2; s++) {
            int k4 = s * 16 + kl;
            ulonglong2 xv[ROWS_PER_WARP];
            #pragma unroll
            for (int p = 0; p < ROWS_PER_WARP; p++)
                xv[p] = xc[(rw0 + p) * KC4 + k4];
            int kg = c * KC4 + k4;
            #pragma unroll
            for (int jj = 0; jj < 5; jj++) {
                if (jj < 4 || jg) {
                    ulonglong2 w = sW2[(jbase + jj) * 256 + kg];
                    #pragma unroll
                    for (int p = 0; p < ROWS_PER_WARP; p++) {
                        acc[p][jj] = fma2(xv[p].x, w.x, acc[p][jj]);
                        acc[p][jj] = fma2(xv[p].y, w.y, acc[p][jj]);
                    }
                }
            }
        }
        mbar_arrive(EMPTYB(st));

        // producer refill: stage st gets chunk c+4
        if (warp == 0 && c + STAGES < NKC) {
            mbar_wait(EMPTYB(st), 0);       // consumed once by all 256 threads
            if (lane == 0) mbar_expect_tx(FULLB(st), xtx);
            __syncwarp();
            if (rowValid)
                bulk_g2s(xsm + (uint32_t)(st * 1024 + lane * KC4) * 16u,
                         rowp + (c + STAGES) * (KC4 * 4), 512u, FULLB(st));
        }
    }

    // ---- reduce over the 16 k-lanes of each half-warp ----
    #pragma unroll
    for (int p = 0; p < ROWS_PER_WARP; p++)
        #pragma unroll
        for (int jj = 0; jj < 5; jj++) {
            u64 a = acc[p][jj];
            #pragma unroll
            for (int off = 8; off >= 1; off >>= 1)
                a = add2(a, __shfl_xor_sync(0xffffffffu, a, off));
            acc[p][jj] = a;
        }

    // ---- epilogue: lane p assembles row p's 9 logits ----
    #pragma unroll
    for (int p = 0; p < ROWS_PER_WARP; p++) {
        float v[5];
        #pragma unroll
        for (int jj = 0; jj < 5; jj++) v[jj] = pair_sum(acc[p][jj]);
        float hi[5];
        #pragma unroll
        for (int jj = 0; jj < 5; jj++)
            hi[jj] = __shfl_xor_sync(0xffffffffu, v[jj], 16);
        if (lane == p) {
            int d = d0 + rw0 + p;
            bool rv = d < nv;
            float l[LL_];
            l[0] = v[0]; l[1] = v[1]; l[2] = v[2]; l[3] = v[3];
            l[4] = hi[0]; l[5] = hi[1]; l[6] = hi[2]; l[7] = hi[3]; l[8] = hi[4];
            float mx = -3.402823466e+38f;
            #pragma unroll
            for (int j = 0; j < LL_; j++) {
                l[j] = rv ? (l[j] + sb[j]) : sb[j];
                mx = fmaxf(mx, l[j]);
            }
            float ssum = 0.0f;
            #pragma unroll
            for (int j = 0; j < LL_; j++) { l[j] = __expf(l[j] - mx); ssum += l[j]; }
            float inv = __fdividef(1.0f, ssum);
            float* o = out + (size_t)(b * SS_ + d) * LL_;
            #pragma unroll
            for (int j = 0; j < LL_; j++) o[j] = l[j] * inv;
        }
    }
}

// ---------------------------------------------------------------------------
#define DYN_SMEM ((LL_ * 256 + STAGES * ROWS_PER_BLOCK * KC4) * 16)   // 102400 B

extern "C" void kernel_launch(void* const* d_in, const int* in_sizes, int n_in,
                              void* d_out, int out_size) {
    const float* seq  = (const float*)d_in[0];   // [B,S,H] f32
    const int*   mask = (const int*)d_in[1];     // [B,S]   i32
    const float* W    = (const float*)d_in[2];   // [H,L]   f32
    const float* bias = (const float*)d_in[3];   // [L]     f32
    float* out = (float*)d_out;                  // [B,S,L] f32

    cudaFuncSetAttribute(bertner_main_kernel,
                         cudaFuncAttributeMaxDynamicSharedMemorySize, DYN_SMEM);

    transpose_W<<<LL_, HH_>>>(W);

    int grid = (BB_ * SS_) / ROWS_PER_BLOCK;     // 1024
    bertner_main_kernel<<<grid, TPB, DYN_SMEM>>>(seq, mask, bias, out);
}

// round 10
// speedup vs baseline: 1.1886x; 1.1886x over previous
#include <cuda_runtime.h>
#include <cuda_bf16.h>
#include <cstdint>

// Problem shape (fixed)
#define BB_ 64
#define SS_ 512
#define HH_ 1024
#define LL_ 9

#define TPB 256
#define WARPS 8
#define ROWS_PER_WARP 2
#define ROWS_PER_BLOCK 16        // 8 warps * 2 rows
#define NCHUNK 16                // 512/32 mask chunks

// Transposed weights [L][H], written once
__device__ float g_Wt[LL_ * HH_];

typedef unsigned long long u64;

__device__ __forceinline__ u64 fma2(u64 a, u64 b, u64 c) {
    u64 d;
    asm("fma.rn.f32x2 %0, %1, %2, %3;" : "=l"(d) : "l"(a), "l"(b), "l"(c));
    return d;
}
__device__ __forceinline__ u64 add2(u64 a, u64 b) {
    u64 d;
    asm("add.rn.f32x2 %0, %1, %2;" : "=l"(d) : "l"(a), "l"(b));
    return d;
}
__device__ __forceinline__ float pair_sum(u64 v) {
    float lo = __uint_as_float((unsigned)(v & 0xffffffffull));
    float hi = __uint_as_float((unsigned)(v >> 32));
    return lo + hi;
}

// ---------------------------------------------------------------------------
// One-shot: W [H,L] -> g_Wt [L,H]
// ---------------------------------------------------------------------------
__global__ void transpose_W(const float* __restrict__ W) {
    int j = blockIdx.x;
    int k = threadIdx.x;
    g_Wt[j * HH_ + k] = W[k * LL_ + j];
}

// ---------------------------------------------------------------------------
// Main kernel. Block = 16 rows of one batch. Warp owns 2 rows; half-warps
// split the 9 outputs (lanes 0-15: j0..3, lanes 16-31: j4..8).
// Hot loop: 4 front-batched LDG.128 (2 rows x 2 k-iters), W from smem,
// f32x2 packed FMA. Tiny register state -> 32 warps/SM + real MLP.
// ---------------------------------------------------------------------------
__global__ __launch_bounds__(TPB, 4)
void bertner_main_kernel(const float* __restrict__ seq,
                         const int* __restrict__ mask,
                         const float* __restrict__ bias,
                         float* __restrict__ out) {
    __shared__ ulonglong2 sW2[LL_ * 256];    // Wt [j][k4], 36 KB
    __shared__ unsigned mbits[NCHUNK];
    __shared__ int msum[NCHUNK];
    __shared__ int ssrc[ROWS_PER_BLOCK];
    __shared__ int snv;
    __shared__ float sb[LL_];

    int tid  = threadIdx.x;
    int lane = tid & 31;
    int warp = tid >> 5;

    int b  = blockIdx.x >> 5;                 // 32 blocks per batch
    int d0 = (blockIdx.x & 31) * ROWS_PER_BLOCK;

    if (tid < LL_) sb[tid] = bias[tid];

    // ---- per-block mask scan (512 bits) ----
    #pragma unroll
    for (int r = 0; r < 2; r++) {
        int chunk = warp * 2 + r;
        int s = chunk * 32 + lane;
        int m = (mask[b * SS_ + s] != 0);
        unsigned bal = __ballot_sync(0xffffffffu, m);
        if (lane == 0) mbits[chunk] = bal;
    }
    __syncthreads();
    if (tid < NCHUNK) {
        int v = __popc(mbits[tid]);
        #pragma unroll
        for (int off = 1; off < NCHUNK; off <<= 1) {
            int u = __shfl_up_sync(0x0000ffffu, v, off);
            if (tid >= off) v += u;
        }
        msum[tid] = v;
        if (tid == NCHUNK - 1) snv = v;
    }
    __syncthreads();
    int nv = snv;

    if (d0 >= nv) {
        // whole block invalid: softmax(bias) for its 16 rows
        if (tid < ROWS_PER_BLOCK) {
            float l[LL_];
            float mx = -3.402823466e+38f;
            #pragma unroll
            for (int j = 0; j < LL_; j++) { l[j] = sb[j]; mx = fmaxf(mx, l[j]); }
            float ssum = 0.0f;
            #pragma unroll
            for (int j = 0; j < LL_; j++) { l[j] = __expf(l[j] - mx); ssum += l[j]; }
            float inv = __fdividef(1.0f, ssum);
            float* o = out + (size_t)(b * SS_ + d0 + tid) * LL_;
            #pragma unroll
            for (int j = 0; j < LL_; j++) o[j] = l[j] * inv;
        }
        return;
    }

    // ---- source index for this block's 16 rows ----
    if (tid < ROWS_PER_BLOCK) {
        int d = d0 + tid;
        int src = 0;
        if (d < nv) {
            int c = 0, base = 0;
            #pragma unroll
            for (int cc = 0; cc < NCHUNK - 1; cc++)
                if (msum[cc] <= d) { c = cc + 1; base = msum[cc]; }
            unsigned wv = mbits[c];
            int rr = d - base;
            for (int t = 0; t < rr; t++) wv &= wv - 1;
            src = c * 32 + (__ffs(wv) - 1);
        }
        ssrc[tid] = src;
    }

    // ---- stage transposed W (conflict-free float4 memcpy) ----
    {
        const float4* s4 = (const float4*)g_Wt;
        float4* dd4 = (float4*)sW2;
        #pragma unroll
        for (int it = 0; it < (LL_ * HH_ / 4) / TPB; it++)   // 9
            dd4[it * TPB + tid] = s4[it * TPB + tid];
    }
    __syncthreads();

    // ---- main GEMV ----
    int jg = lane >> 4;                        // 0: j0..3, 1: j4..8
    int kl = lane & 15;
    int jbase = jg * 4;

    int rw0 = warp * ROWS_PER_WARP;
    int dr0 = d0 + rw0;
    bool v0 = dr0 < nv;
    bool v1 = (dr0 + 1) < nv;

    const float4* x0 = (const float4*)seq + ((size_t)(b * SS_ + ssrc[rw0 + 0]) * 256);
    const float4* x1 = (const float4*)seq + ((size_t)(b * SS_ + ssrc[rw0 + 1]) * 256);

    u64 acc0[5], acc1[5];
    #pragma unroll
    for (int jj = 0; jj < 5; jj++) { acc0[jj] = 0ull; acc1[jj] = 0ull; }

    if (v0 || v1) {
        #pragma unroll
        for (int i = 0; i < 8; i++) {
            int k4a = i * 32 + kl;             // two k-iters per step
            int k4b = k4a + 16;
            // front-batch all 4 LDG.128 before any use
            float4 a0 = make_float4(0.f, 0.f, 0.f, 0.f);
            float4 b0 = make_float4(0.f, 0.f, 0.f, 0.f);
            float4 a1 = make_float4(0.f, 0.f, 0.f, 0.f);
            float4 b1 = make_float4(0.f, 0.f, 0.f, 0.f);
            if (v0) { a0 = x0[k4a]; b0 = x0[k4b]; }
            if (v1) { a1 = x1[k4a]; b1 = x1[k4b]; }
            ulonglong2 xa0 = *(ulonglong2*)&a0;
            ulonglong2 xb0 = *(ulonglong2*)&b0;
            ulonglong2 xa1 = *(ulonglong2*)&a1;
            ulonglong2 xb1 = *(ulonglong2*)&b1;
            #pragma unroll
            for (int jj = 0; jj < 5; jj++) {
                if (jj < 4 || jg) {
                    ulonglong2 wA = sW2[(jbase + jj) * 256 + k4a];
                    acc0[jj] = fma2(xa0.x, wA.x, acc0[jj]);
                    acc0[jj] = fma2(xa0.y, wA.y, acc0[jj]);
                    acc1[jj] = fma2(xa1.x, wA.x, acc1[jj]);
                    acc1[jj] = fma2(xa1.y, wA.y, acc1[jj]);
                    ulonglong2 wB = sW2[(jbase + jj) * 256 + k4b];
                    acc0[jj] = fma2(xb0.x, wB.x, acc0[jj]);
                    acc0[jj] = fma2(xb0.y, wB.y, acc0[jj]);
                    acc1[jj] = fma2(xb1.x, wB.x, acc1[jj]);
                    acc1[jj] = fma2(xb1.y, wB.y, acc1[jj]);
                }
            }
        }
        // reduce over the 16 k-lanes of each half-warp
        #pragma unroll
        for (int jj = 0; jj < 5; jj++) {
            u64 a = acc0[jj];
            u64 c = acc1[jj];
            #pragma unroll
            for (int off = 8; off >= 1; off >>= 1) {
                a = add2(a, __shfl_xor_sync(0xffffffffu, a, off));
                c = add2(c, __shfl_xor_sync(0xffffffffu, c, off));
            }
            acc0[jj] = a;
            acc1[jj] = c;
        }
    }

    // ---- epilogue (FIXED): every lane reduces BOTH rows' pairs, so the
    // jg=1 half-warp supplies the correct per-row j4..8 values via shfl ----
    float va[5], vb[5];
    #pragma unroll
    for (int jj = 0; jj < 5; jj++) {
        va[jj] = pair_sum(acc0[jj]);
        vb[jj] = pair_sum(acc1[jj]);
    }
    float ha[5], hb[5];
    #pragma unroll
    for (int jj = 0; jj < 5; jj++) {
        ha[jj] = __shfl_xor_sync(0xffffffffu, va[jj], 16);
        hb[jj] = __shfl_xor_sync(0xffffffffu, vb[jj], 16);
    }
    if (lane < ROWS_PER_WARP) {
        float l[LL_];
        if (lane == 0) {
            l[0] = va[0]; l[1] = va[1]; l[2] = va[2]; l[3] = va[3];
            l[4] = ha[0]; l[5] = ha[1]; l[6] = ha[2]; l[7] = ha[3]; l[8] = ha[4];
        } else {
            l[0] = vb[0]; l[1] = vb[1]; l[2] = vb[2]; l[3] = vb[3];
            l[4] = hb[0]; l[5] = hb[1]; l[6] = hb[2]; l[7] = hb[3]; l[8] = hb[4];
        }
        float mx = -3.402823466e+38f;
        #pragma unroll
        for (int j = 0; j < LL_; j++) { l[j] += sb[j]; mx = fmaxf(mx, l[j]); }
        float ssum = 0.0f;
        #pragma unroll
        for (int j = 0; j < LL_; j++) { l[j] = __expf(l[j] - mx); ssum += l[j]; }
        float inv = __fdividef(1.0f, ssum);
        float* o = out + (size_t)(b * SS_ + dr0 + lane) * LL_;
        #pragma unroll
        for (int j = 0; j < LL_; j++) o[j] = l[j] * inv;
    }
}

// ---------------------------------------------------------------------------
extern "C" void kernel_launch(void* const* d_in, const int* in_sizes, int n_in,
                              void* d_out, int out_size) {
    const float* seq  = (const float*)d_in[0];   // [B,S,H] f32
    const int*   mask = (const int*)d_in[1];     // [B,S]   i32
    const float* W    = (const float*)d_in[2];   // [H,L]   f32
    const float* bias = (const float*)d_in[3];   // [L]     f32
    float* out = (float*)d_out;                  // [B,S,L] f32

    transpose_W<<<LL_, HH_>>>(W);

    int grid = (BB_ * SS_) / ROWS_PER_BLOCK;     // 2048
    bertner_main_kernel<<<grid, TPB>>>(seq, mask, bias, out);
}